// round 3
// baseline (speedup 1.0000x reference)
#include <cuda_runtime.h>
#include <math.h>

// Problem constants
#define EMBED  1024
#define INDIM  256
#define HID    256
#define NVIEW  6
#define NROWS  49152   // B*M*NVIEW = 32*256*6
#define NBM    8192    // B*M

// Scratch (allocation-free: __device__ globals)
__device__ float g_bufA[(size_t)NROWS * EMBED];  // GEMM1 out, then gates buffer (201 MB)
__device__ float g_bufX[(size_t)NROWS * INDIM];  // LSTM activations (50 MB)
__device__ float g_h[NBM * HID];
__device__ float g_c[NBM * HID];
__device__ float g_score[NBM];

// ---------------------------------------------------------------------------
// Generic C = A @ B^T  (A:[M,K] row-major lda, B:[N,K] row-major ldb)
// Tile 128x128x16, 256 threads, 8x8 per-thread microtile.
// EPI 0: C = resid + gelu_exact(acc + bias0)        (GEMM1)
// EPI 1: C = acc + bias0                            (GEMM2)
// EPI 2: C = acc + bias0 + bias1                    (LSTM input proj)
// EPI 3: C += acc                                   (recurrent accumulate)
// Requires: M%128==0, N%128==0, K%16==0, lda/ldb/ldc multiples of 4.
// ---------------------------------------------------------------------------
template <int EPI>
__global__ __launch_bounds__(256) void sgemm_kernel(
    const float* __restrict__ A, int lda,
    const float* __restrict__ B, int ldb,
    float* __restrict__ C, int ldc,
    int K,
    const float* __restrict__ bias0,
    const float* __restrict__ bias1,
    const float* __restrict__ resid)
{
    __shared__ __align__(16) float As[16][132];
    __shared__ __align__(16) float Bs[16][132];

    const int tid  = threadIdx.x;
    const int bx   = blockIdx.x;   // N tile
    const int by   = blockIdx.y;   // M tile
    const int lrow = tid >> 2;          // 0..63
    const int kc   = (tid & 3) * 4;     // 0,4,8,12
    const int wrow = (tid >> 4) * 8;    // 0..120
    const int wcol = (tid & 15) * 8;    // 0..120

    const float* Ap = A + (size_t)(by * 128 + lrow) * lda + kc;
    const float* Bp = B + (size_t)(bx * 128 + lrow) * ldb + kc;

    float acc[8][8];
#pragma unroll
    for (int i = 0; i < 8; i++)
#pragma unroll
        for (int j = 0; j < 8; j++) acc[i][j] = 0.f;

    for (int k0 = 0; k0 < K; k0 += 16) {
#pragma unroll
        for (int p = 0; p < 2; p++) {
            float4 va = *reinterpret_cast<const float4*>(Ap + (size_t)p * 64 * lda + k0);
            As[kc + 0][lrow + p * 64] = va.x;
            As[kc + 1][lrow + p * 64] = va.y;
            As[kc + 2][lrow + p * 64] = va.z;
            As[kc + 3][lrow + p * 64] = va.w;
            float4 vb = *reinterpret_cast<const float4*>(Bp + (size_t)p * 64 * ldb + k0);
            Bs[kc + 0][lrow + p * 64] = vb.x;
            Bs[kc + 1][lrow + p * 64] = vb.y;
            Bs[kc + 2][lrow + p * 64] = vb.z;
            Bs[kc + 3][lrow + p * 64] = vb.w;
        }
        __syncthreads();
#pragma unroll
        for (int k = 0; k < 16; k++) {
            float4 a0 = *reinterpret_cast<const float4*>(&As[k][wrow]);
            float4 a1 = *reinterpret_cast<const float4*>(&As[k][wrow + 4]);
            float4 b0 = *reinterpret_cast<const float4*>(&Bs[k][wcol]);
            float4 b1 = *reinterpret_cast<const float4*>(&Bs[k][wcol + 4]);
            float a[8] = {a0.x, a0.y, a0.z, a0.w, a1.x, a1.y, a1.z, a1.w};
            float b[8] = {b0.x, b0.y, b0.z, b0.w, b1.x, b1.y, b1.z, b1.w};
#pragma unroll
            for (int i = 0; i < 8; i++)
#pragma unroll
                for (int j = 0; j < 8; j++) acc[i][j] = fmaf(a[i], b[j], acc[i][j]);
        }
        __syncthreads();
    }

#pragma unroll
    for (int i = 0; i < 8; i++) {
        const int gr = by * 128 + wrow + i;
        const size_t rowoff = (size_t)gr * ldc;
#pragma unroll
        for (int j = 0; j < 8; j++) {
            const int gc = bx * 128 + wcol + j;
            float v = acc[i][j];
            if (EPI == 0) {
                v += bias0[gc];
                float g = 0.5f * v * (1.f + erff(v * 0.70710678118654752f));
                v = g + resid[rowoff + gc];
            } else if (EPI == 1) {
                v += bias0[gc];
            } else if (EPI == 2) {
                v += bias0[gc] + bias1[gc];
            } else {
                v += C[rowoff + gc];
            }
            C[rowoff + gc] = v;
        }
    }
}

// ---------------------------------------------------------------------------
// LSTM pointwise cell update at timestep t.
// gates layout: gb[(bm*6+t)*1024 + {j, 256+j, 512+j, 768+j}] = i,f,g,o
// Writes h, c, and h into X[(bm*6+t)*256 + j] (next-layer input / final feats).
// ---------------------------------------------------------------------------
__global__ __launch_bounds__(256) void lstm_cell_kernel(
    const float* __restrict__ gb, float* __restrict__ h, float* __restrict__ c,
    float* __restrict__ X, int t, int first)
{
    const int idx = blockIdx.x * blockDim.x + threadIdx.x;  // 8192*256
    const int bm = idx >> 8;
    const int j  = idx & 255;
    const float* g = gb + (size_t)(bm * 6 + t) * 1024;
    const float gi = g[j];
    const float gf = g[j + 256];
    const float gg = g[j + 512];
    const float go = g[j + 768];
    const float si = 1.f / (1.f + expf(-gi));
    const float sf = 1.f / (1.f + expf(-gf));
    const float so = 1.f / (1.f + expf(-go));
    const float cold = first ? 0.f : c[idx];
    const float cn = sf * cold + si * tanhf(gg);
    const float hn = so * tanhf(cn);
    c[idx] = cn;
    h[idx] = hn;
    X[(size_t)(bm * 6 + t) * 256 + j] = hn;
}

// score[bm] = sum_t Ws[t]*(dot(X[bm*6+t], Wv) + bv) + bs ; 1 warp per bm
__global__ __launch_bounds__(256) void final1_kernel(
    const float* __restrict__ X, const float* __restrict__ Wv,
    const float* __restrict__ bv, const float* __restrict__ Ws,
    const float* __restrict__ bs, float* __restrict__ score)
{
    const int warp = threadIdx.x >> 5;
    const int lane = threadIdx.x & 31;
    const int bm = blockIdx.x * 8 + warp;
    float wv[8];
#pragma unroll
    for (int u = 0; u < 8; u++) wv[u] = Wv[lane + u * 32];
    float acc = 0.f;
#pragma unroll
    for (int t = 0; t < 6; t++) {
        const float* row = X + (size_t)(bm * 6 + t) * 256;
        float p = 0.f;
#pragma unroll
        for (int u = 0; u < 8; u++) p = fmaf(row[lane + u * 32], wv[u], p);
#pragma unroll
        for (int o = 16; o; o >>= 1) p += __shfl_xor_sync(0xFFFFFFFFu, p, o);
        acc = fmaf(Ws[t], p + bv[0], acc);
    }
    if (lane == 0) score[bm] = acc + bs[0];
}

// out[b] = mean_m score[b*256+m]
__global__ __launch_bounds__(256) void final2_kernel(
    const float* __restrict__ score, float* __restrict__ out)
{
    __shared__ float s[256];
    s[threadIdx.x] = score[blockIdx.x * 256 + threadIdx.x];
    __syncthreads();
    for (int o = 128; o; o >>= 1) {
        if (threadIdx.x < o) s[threadIdx.x] += s[threadIdx.x + o];
        __syncthreads();
    }
    if (threadIdx.x == 0) out[blockIdx.x] = s[0] * (1.f / 256.f);
}

extern "C" void kernel_launch(void* const* d_in, const int* in_sizes, int n_in,
                              void* d_out, int out_size)
{
    (void)in_sizes; (void)n_in; (void)out_size;
    const float* swin = (const float*)d_in[0];   // [32,256,6,1024]
    const float* conv = (const float*)d_in[1];   // [32,256,6,1024]
    const float* Wc   = (const float*)d_in[2];   // [1024,1024]
    const float* bc   = (const float*)d_in[3];   // [1024]
    const float* Win  = (const float*)d_in[4];   // [256,1024]
    const float* b_in = (const float*)d_in[5];   // [256]
    const float* Wih  = (const float*)d_in[6];   // [3,1024,256]
    const float* Whh  = (const float*)d_in[7];   // [3,1024,256]
    const float* bih  = (const float*)d_in[8];   // [3,1024]
    const float* bhh  = (const float*)d_in[9];   // [3,1024]
    const float* Wv   = (const float*)d_in[10];  // [1,256]
    const float* bv   = (const float*)d_in[11];  // [1]
    const float* Ws   = (const float*)d_in[12];  // [1,6]
    const float* bs   = (const float*)d_in[13];  // [1]
    float* out = (float*)d_out;

    float *bufA, *bufX, *h, *c, *score;
    cudaGetSymbolAddress((void**)&bufA, g_bufA);
    cudaGetSymbolAddress((void**)&bufX, g_bufX);
    cudaGetSymbolAddress((void**)&h, g_h);
    cudaGetSymbolAddress((void**)&c, g_c);
    cudaGetSymbolAddress((void**)&score, g_score);

    // 1) bufA = swin + gelu(conv @ Wc^T + bc)   [49152,1024]
    sgemm_kernel<0><<<dim3(EMBED / 128, NROWS / 128), 256>>>(
        conv, EMBED, Wc, EMBED, bufA, EMBED, EMBED, bc, nullptr, swin);

    // 2) bufX = bufA @ Win^T + b_in             [49152,256]
    sgemm_kernel<1><<<dim3(INDIM / 128, NROWS / 128), 256>>>(
        bufA, EMBED, Win, EMBED, bufX, INDIM, EMBED, b_in, nullptr, nullptr);

    // 3) LSTM layers
    for (int l = 0; l < 3; l++) {
        const float* WihL = Wih + (size_t)l * 4 * HID * INDIM;
        const float* WhhL = Whh + (size_t)l * 4 * HID * HID;
        // gates (input proj for all timesteps): bufA = bufX @ Wih^T + bih + bhh
        sgemm_kernel<2><<<dim3(4 * HID / 128, NROWS / 128), 256>>>(
            bufX, INDIM, WihL, INDIM, bufA, 4 * HID, INDIM,
            bih + l * 4 * HID, bhh + l * 4 * HID, nullptr);
        for (int t = 0; t < 6; t++) {
            if (t > 0) {
                // gates[:,t] += h @ Whh^T   (C strided over timesteps, ldc=6*1024)
                sgemm_kernel<3><<<dim3(4 * HID / 128, NBM / 128), 256>>>(
                    h, HID, WhhL, HID, bufA + t * 4 * HID, NVIEW * 4 * HID, HID,
                    nullptr, nullptr, nullptr);
            }
            lstm_cell_kernel<<<NBM * HID / 256, 256>>>(bufA, h, c, bufX, t, t == 0 ? 1 : 0);
        }
    }

    // 4) heads + reduction
    final1_kernel<<<NBM / 8, 256>>>(bufX, Wv, bv, Ws, bs, score);
    final2_kernel<<<32, 256>>>(score, out);
}

// round 5
// speedup vs baseline: 2.0293x; 2.0293x over previous
#include <cuda_runtime.h>
#include <cuda_bf16.h>
#include <math.h>

// Problem constants
#define EMBED  1024
#define INDIM  256
#define HID    256
#define NVIEW  6
#define NROWS  49152   // B*M*NVIEW
#define NBM    8192    // B*M

#define LDSK32 20      // u32 stride per smem row (= 40 bf16: 32 data + 8 pad)

// Scratch (allocation-free: __device__ globals)
__device__ float g_bufA[(size_t)NROWS * EMBED];  // GEMM1 out, then gates buffer
__device__ float g_bufX[(size_t)NROWS * INDIM];  // LSTM activations
__device__ float g_h[NBM * HID];
__device__ float g_c[NBM * HID];
__device__ float g_score[NBM];

__device__ __forceinline__ void mma16816(float* d, const unsigned* a, const unsigned* b)
{
    asm volatile(
        "mma.sync.aligned.m16n8k16.row.col.f32.bf16.bf16.f32 "
        "{%0,%1,%2,%3}, {%4,%5,%6,%7}, {%8,%9}, {%0,%1,%2,%3};\n"
        : "+f"(d[0]), "+f"(d[1]), "+f"(d[2]), "+f"(d[3])
        : "r"(a[0]), "r"(a[1]), "r"(a[2]), "r"(a[3]), "r"(b[0]), "r"(b[1]));
}

// Convert float4 (k..k+3 of one row) into hi/lo bf16 pairs in smem.
// Layout per row (u32 units): [0..7] = hi (16 bf16), [8..15] = lo (16 bf16).
__device__ __forceinline__ void cvt_store(unsigned* S32, int row, int kc, float4 v)
{
    __nv_bfloat16 hx = __float2bfloat16_rn(v.x);
    __nv_bfloat16 hy = __float2bfloat16_rn(v.y);
    __nv_bfloat16 hz = __float2bfloat16_rn(v.z);
    __nv_bfloat16 hw = __float2bfloat16_rn(v.w);
    __nv_bfloat162 h01; h01.x = hx; h01.y = hy;
    __nv_bfloat162 h23; h23.x = hz; h23.y = hw;
    __nv_bfloat162 l01;
    l01.x = __float2bfloat16_rn(v.x - __bfloat162float(hx));
    l01.y = __float2bfloat16_rn(v.y - __bfloat162float(hy));
    __nv_bfloat162 l23;
    l23.x = __float2bfloat16_rn(v.z - __bfloat162float(hz));
    l23.y = __float2bfloat16_rn(v.w - __bfloat162float(hw));
    const int base = row * LDSK32 + (kc >> 1);
    S32[base]     = *reinterpret_cast<unsigned*>(&h01);
    S32[base + 1] = *reinterpret_cast<unsigned*>(&h23);
    S32[base + 8] = *reinterpret_cast<unsigned*>(&l01);
    S32[base + 9] = *reinterpret_cast<unsigned*>(&l23);
}

// ---------------------------------------------------------------------------
// C = A @ B^T via bf16x3-split tensor-core MMA (fp32-accurate to ~1e-5).
// A:[M,K] lda, B:[N,K] ldb, both fp32 row-major. Tile 128x128x16.
// 8 warps: warp grid 2(M)x4(N), warp tile 64x32 = 4x4 m16n8k16 accumulators.
// EPI 0: C = resid + gelu_exact(acc + bias0)
// EPI 1: C = acc + bias0
// EPI 2: C = acc + bias0 + bias1
// EPI 3: C += acc
// Requires M%128==0, N%128==0, K%16==0.
// ---------------------------------------------------------------------------
template <int EPI>
__global__ __launch_bounds__(256) void bgemm_kernel(
    const float* __restrict__ A, int lda,
    const float* __restrict__ B, int ldb,
    float* __restrict__ C, int ldc,
    int K,
    const float* __restrict__ bias0,
    const float* __restrict__ bias1,
    const float* __restrict__ resid)
{
    __shared__ __align__(16) unsigned As32[128 * LDSK32];
    __shared__ __align__(16) unsigned Bs32[128 * LDSK32];

    const int tid  = threadIdx.x;
    const int bx   = blockIdx.x;   // N tile
    const int by   = blockIdx.y;   // M tile
    const int warp = tid >> 5;
    const int lane = tid & 31;
    const int g    = lane >> 2;    // group row
    const int tg   = lane & 3;     // thread-in-group
    const int warpM = (warp & 1) * 64;
    const int warpN = (warp >> 1) * 32;

    // global loader mapping (2 float4 per matrix per thread per k-step)
    const int lrow = tid >> 2;         // 0..63
    const int kc   = (tid & 3) * 4;    // 0,4,8,12

    const float* Ap = A + (size_t)(by * 128 + lrow) * lda + kc;
    const float* Bp = B + (size_t)(bx * 128 + lrow) * ldb + kc;

    float acc[4][4][4];
#pragma unroll
    for (int mt = 0; mt < 4; mt++)
#pragma unroll
        for (int nt = 0; nt < 4; nt++)
#pragma unroll
            for (int e = 0; e < 4; e++) acc[mt][nt][e] = 0.f;

    float4 pa0 = *reinterpret_cast<const float4*>(Ap);
    float4 pa1 = *reinterpret_cast<const float4*>(Ap + (size_t)64 * lda);
    float4 pb0 = *reinterpret_cast<const float4*>(Bp);
    float4 pb1 = *reinterpret_cast<const float4*>(Bp + (size_t)64 * ldb);

    for (int k0 = 0; k0 < K; k0 += 16) {
        cvt_store(As32, lrow,      kc, pa0);
        cvt_store(As32, lrow + 64, kc, pa1);
        cvt_store(Bs32, lrow,      kc, pb0);
        cvt_store(Bs32, lrow + 64, kc, pb1);
        __syncthreads();

        if (k0 + 16 < K) {  // prefetch next chunk, overlapped with MMAs
            pa0 = *reinterpret_cast<const float4*>(Ap + k0 + 16);
            pa1 = *reinterpret_cast<const float4*>(Ap + (size_t)64 * lda + k0 + 16);
            pb0 = *reinterpret_cast<const float4*>(Bp + k0 + 16);
            pb1 = *reinterpret_cast<const float4*>(Bp + (size_t)64 * ldb + k0 + 16);
        }

        // 3 split passes: (Ah,Bh), (Al,Bh), (Ah,Bl); lo slab at u32 offset 8
#pragma unroll
        for (int s = 0; s < 3; s++) {
            const int ao = (s == 1) ? 8 : 0;
            const int bo = (s == 2) ? 8 : 0;
            unsigned af[4][4], bfr[4][2];
#pragma unroll
            for (int mt = 0; mt < 4; mt++) {
                const int r = warpM + mt * 16;
                af[mt][0] = As32[(r + g)     * LDSK32 + ao + tg];
                af[mt][1] = As32[(r + g + 8) * LDSK32 + ao + tg];
                af[mt][2] = As32[(r + g)     * LDSK32 + ao + 4 + tg];
                af[mt][3] = As32[(r + g + 8) * LDSK32 + ao + 4 + tg];
            }
#pragma unroll
            for (int nt = 0; nt < 4; nt++) {
                const int cc = warpN + nt * 8;
                bfr[nt][0] = Bs32[(cc + g) * LDSK32 + bo + tg];
                bfr[nt][1] = Bs32[(cc + g) * LDSK32 + bo + 4 + tg];
            }
#pragma unroll
            for (int mt = 0; mt < 4; mt++)
#pragma unroll
                for (int nt = 0; nt < 4; nt++)
                    mma16816(acc[mt][nt], af[mt], bfr[nt]);
        }
        __syncthreads();
    }

    // epilogue
#pragma unroll
    for (int mt = 0; mt < 4; mt++) {
#pragma unroll
        for (int nt = 0; nt < 4; nt++) {
            const float* d = acc[mt][nt];
            const int col = bx * 128 + warpN + nt * 8 + tg * 2;
#pragma unroll
            for (int half = 0; half < 2; half++) {
                const int gr = by * 128 + warpM + mt * 16 + g + half * 8;
                const size_t rowoff = (size_t)gr * ldc;
#pragma unroll
                for (int e = 0; e < 2; e++) {
                    const int gc = col + e;
                    float v = d[half * 2 + e];
                    if (EPI == 0) {
                        v += bias0[gc];
                        float ge = 0.5f * v * (1.f + erff(v * 0.70710678118654752f));
                        v = ge + resid[rowoff + gc];
                    } else if (EPI == 1) {
                        v += bias0[gc];
                    } else if (EPI == 2) {
                        v += bias0[gc] + bias1[gc];
                    } else {
                        v += C[rowoff + gc];
                    }
                    C[rowoff + gc] = v;
                }
            }
        }
    }
}

// ---------------------------------------------------------------------------
// LSTM pointwise cell update at timestep t (unchanged).
// ---------------------------------------------------------------------------
__global__ __launch_bounds__(256) void lstm_cell_kernel(
    const float* __restrict__ gb, float* __restrict__ h, float* __restrict__ c,
    float* __restrict__ X, int t, int first)
{
    const int idx = blockIdx.x * blockDim.x + threadIdx.x;
    const int bm = idx >> 8;
    const int j  = idx & 255;
    const float* g = gb + (size_t)(bm * 6 + t) * 1024;
    const float gi = g[j];
    const float gf = g[j + 256];
    const float gg = g[j + 512];
    const float go = g[j + 768];
    const float si = 1.f / (1.f + expf(-gi));
    const float sf = 1.f / (1.f + expf(-gf));
    const float so = 1.f / (1.f + expf(-go));
    const float cold = first ? 0.f : c[idx];
    const float cn = sf * cold + si * tanhf(gg);
    const float hn = so * tanhf(cn);
    c[idx] = cn;
    h[idx] = hn;
    X[(size_t)(bm * 6 + t) * 256 + j] = hn;
}

__global__ __launch_bounds__(256) void final1_kernel(
    const float* __restrict__ X, const float* __restrict__ Wv,
    const float* __restrict__ bv, const float* __restrict__ Ws,
    const float* __restrict__ bs, float* __restrict__ score)
{
    const int warp = threadIdx.x >> 5;
    const int lane = threadIdx.x & 31;
    const int bm = blockIdx.x * 8 + warp;
    float wv[8];
#pragma unroll
    for (int u = 0; u < 8; u++) wv[u] = Wv[lane + u * 32];
    float acc = 0.f;
#pragma unroll
    for (int t = 0; t < 6; t++) {
        const float* row = X + (size_t)(bm * 6 + t) * 256;
        float p = 0.f;
#pragma unroll
        for (int u = 0; u < 8; u++) p = fmaf(row[lane + u * 32], wv[u], p);
#pragma unroll
        for (int o = 16; o; o >>= 1) p += __shfl_xor_sync(0xFFFFFFFFu, p, o);
        acc = fmaf(Ws[t], p + bv[0], acc);
    }
    if (lane == 0) score[bm] = acc + bs[0];
}

__global__ __launch_bounds__(256) void final2_kernel(
    const float* __restrict__ score, float* __restrict__ out)
{
    __shared__ float s[256];
    s[threadIdx.x] = score[blockIdx.x * 256 + threadIdx.x];
    __syncthreads();
    for (int o = 128; o; o >>= 1) {
        if (threadIdx.x < o) s[threadIdx.x] += s[threadIdx.x + o];
        __syncthreads();
    }
    if (threadIdx.x == 0) out[blockIdx.x] = s[0] * (1.f / 256.f);
}

extern "C" void kernel_launch(void* const* d_in, const int* in_sizes, int n_in,
                              void* d_out, int out_size)
{
    (void)in_sizes; (void)n_in; (void)out_size;
    const float* swin = (const float*)d_in[0];
    const float* conv = (const float*)d_in[1];
    const float* Wc   = (const float*)d_in[2];
    const float* bc   = (const float*)d_in[3];
    const float* Win  = (const float*)d_in[4];
    const float* b_in = (const float*)d_in[5];
    const float* Wih  = (const float*)d_in[6];
    const float* Whh  = (const float*)d_in[7];
    const float* bih  = (const float*)d_in[8];
    const float* bhh  = (const float*)d_in[9];
    const float* Wv   = (const float*)d_in[10];
    const float* bv   = (const float*)d_in[11];
    const float* Ws   = (const float*)d_in[12];
    const float* bs   = (const float*)d_in[13];
    float* out = (float*)d_out;

    float *bufA, *bufX, *h, *c, *score;
    cudaGetSymbolAddress((void**)&bufA, g_bufA);
    cudaGetSymbolAddress((void**)&bufX, g_bufX);
    cudaGetSymbolAddress((void**)&h, g_h);
    cudaGetSymbolAddress((void**)&c, g_c);
    cudaGetSymbolAddress((void**)&score, g_score);

    // 1) bufA = swin + gelu(conv @ Wc^T + bc)   [49152,1024]
    bgemm_kernel<0><<<dim3(EMBED / 128, NROWS / 128), 256>>>(
        conv, EMBED, Wc, EMBED, bufA, EMBED, EMBED, bc, nullptr, swin);

    // 2) bufX = bufA @ Win^T + b_in             [49152,256]
    bgemm_kernel<1><<<dim3(INDIM / 128, NROWS / 128), 256>>>(
        bufA, EMBED, Win, EMBED, bufX, INDIM, EMBED, b_in, nullptr, nullptr);

    // 3) LSTM layers
    for (int l = 0; l < 3; l++) {
        const float* WihL = Wih + (size_t)l * 4 * HID * INDIM;
        const float* WhhL = Whh + (size_t)l * 4 * HID * HID;
        bgemm_kernel<2><<<dim3(4 * HID / 128, NROWS / 128), 256>>>(
            bufX, INDIM, WihL, INDIM, bufA, 4 * HID, INDIM,
            bih + l * 4 * HID, bhh + l * 4 * HID, nullptr);
        for (int t = 0; t < 6; t++) {
            if (t > 0) {
                bgemm_kernel<3><<<dim3(4 * HID / 128, NBM / 128), 256>>>(
                    h, HID, WhhL, HID, bufA + t * 4 * HID, NVIEW * 4 * HID, HID,
                    nullptr, nullptr, nullptr);
            }
            lstm_cell_kernel<<<NBM * HID / 256, 256>>>(bufA, h, c, bufX, t, t == 0 ? 1 : 0);
        }
    }

    // 4) heads + reduction
    final1_kernel<<<NBM / 8, 256>>>(bufX, Wv, bv, Ws, bs, score);
    final2_kernel<<<32, 256>>>(score, out);
}

// round 7
// speedup vs baseline: 2.4395x; 1.2021x over previous
#include <cuda_runtime.h>
#include <cuda_bf16.h>
#include <math.h>

// Problem constants
#define EMBED  1024
#define INDIM  256
#define HID    256
#define NVIEW  6
#define NROWS  49152   // B*M*NVIEW
#define NBM    8192    // B*M

#define LDSK32 20              // u32 per smem row (32 data bf16-pairs + pad)
#define STAGE_U32 (128 * LDSK32)

// Scratch (allocation-free: __device__ globals)
__device__ float g_bufA[(size_t)NROWS * EMBED];
__device__ float g_bufX[(size_t)NROWS * INDIM];
__device__ float g_h[NBM * HID];
__device__ float g_c[NBM * HID];
__device__ float g_score[NBM];

__device__ __forceinline__ void mma16816(float* d, const unsigned* a, const unsigned* b)
{
    asm volatile(
        "mma.sync.aligned.m16n8k16.row.col.f32.bf16.bf16.f32 "
        "{%0,%1,%2,%3}, {%4,%5,%6,%7}, {%8,%9}, {%0,%1,%2,%3};\n"
        : "+f"(d[0]), "+f"(d[1]), "+f"(d[2]), "+f"(d[3])
        : "r"(a[0]), "r"(a[1]), "r"(a[2]), "r"(a[3]), "r"(b[0]), "r"(b[1]));
}

__device__ __forceinline__ void ldsm_x4(unsigned& r0, unsigned& r1, unsigned& r2,
                                        unsigned& r3, unsigned addr)
{
    asm volatile("ldmatrix.sync.aligned.m8n8.x4.shared.b16 {%0,%1,%2,%3}, [%4];\n"
                 : "=r"(r0), "=r"(r1), "=r"(r2), "=r"(r3) : "r"(addr));
}

// Convert float4 (k..k+3 of one row) into hi/lo bf16 pairs in smem stage.
// Row layout (u32): [0..7] hi (16 bf16), [8..15] lo, [16..19] pad.
__device__ __forceinline__ void cvt_store(unsigned* S32, int row, int kc, float4 v)
{
    __nv_bfloat16 hx = __float2bfloat16_rn(v.x);
    __nv_bfloat16 hy = __float2bfloat16_rn(v.y);
    __nv_bfloat16 hz = __float2bfloat16_rn(v.z);
    __nv_bfloat16 hw = __float2bfloat16_rn(v.w);
    __nv_bfloat162 h01; h01.x = hx; h01.y = hy;
    __nv_bfloat162 h23; h23.x = hz; h23.y = hw;
    __nv_bfloat162 l01;
    l01.x = __float2bfloat16_rn(v.x - __bfloat162float(hx));
    l01.y = __float2bfloat16_rn(v.y - __bfloat162float(hy));
    __nv_bfloat162 l23;
    l23.x = __float2bfloat16_rn(v.z - __bfloat162float(hz));
    l23.y = __float2bfloat16_rn(v.w - __bfloat162float(hw));
    const int base = row * LDSK32 + (kc >> 1);
    uint2 hi; hi.x = *reinterpret_cast<unsigned*>(&h01); hi.y = *reinterpret_cast<unsigned*>(&h23);
    uint2 lo; lo.x = *reinterpret_cast<unsigned*>(&l01); lo.y = *reinterpret_cast<unsigned*>(&l23);
    *reinterpret_cast<uint2*>(S32 + base)     = hi;
    *reinterpret_cast<uint2*>(S32 + base + 8) = lo;
}

// ---------------------------------------------------------------------------
// C = A @ B^T via bf16x3-split tensor-core MMA. Tile 128x128x16, 8 warps
// (2Mx4N), warp tile 64x32. Double-buffered smem, ldmatrix fragment loads.
// EPI 0: C = resid + gelu_exact(acc+bias0)   EPI 1: C = acc+bias0
// EPI 2: C = acc+bias0+bias1                 EPI 3: C += acc
// ---------------------------------------------------------------------------
template <int EPI>
__global__ __launch_bounds__(256, 2) void bgemm_kernel(
    const float* __restrict__ A, int lda,
    const float* __restrict__ B, int ldb,
    float* __restrict__ C, int ldc,
    int K,
    const float* __restrict__ bias0,
    const float* __restrict__ bias1,
    const float* __restrict__ resid)
{
    __shared__ __align__(16) unsigned As32[2 * STAGE_U32];
    __shared__ __align__(16) unsigned Bs32[2 * STAGE_U32];

    const int tid  = threadIdx.x;
    const int bx   = blockIdx.x;
    const int by   = blockIdx.y;
    const int warp = tid >> 5;
    const int lane = tid & 31;
    const int g    = lane >> 2;
    const int tg   = lane & 3;
    const int warpM = (warp & 1) * 64;
    const int warpN = (warp >> 1) * 32;

    // global loader mapping
    const int lrow = tid >> 2;
    const int kc   = (tid & 3) * 4;

    const float* Ap = A + (size_t)(by * 128 + lrow) * lda + kc;
    const float* Bp = B + (size_t)(bx * 128 + lrow) * ldb + kc;

    // ldmatrix lane addresses (bytes into smem)
    const unsigned asmem = (unsigned)__cvta_generic_to_shared(As32);
    const unsigned bsmem = (unsigned)__cvta_generic_to_shared(Bs32);
    unsigned aAddr[4], bAddr[2];
#pragma unroll
    for (int mt = 0; mt < 4; mt++) {
        const int r = warpM + mt * 16 + (lane & 15);
        aAddr[mt] = asmem + r * (LDSK32 * 4) + ((lane >> 4) & 1) * 16;
    }
#pragma unroll
    for (int p = 0; p < 2; p++) {
        const int r = warpN + p * 16 + (lane & 7) + ((lane >> 4) & 1) * 8;
        bAddr[p] = bsmem + r * (LDSK32 * 4) + ((lane >> 3) & 1) * 16;
    }

    float acc[4][4][4];
#pragma unroll
    for (int mt = 0; mt < 4; mt++)
#pragma unroll
        for (int nt = 0; nt < 4; nt++)
#pragma unroll
            for (int e = 0; e < 4; e++) acc[mt][nt][e] = 0.f;

    // prologue: load + convert k-chunk 0 into stage 0
    float4 pa0 = *reinterpret_cast<const float4*>(Ap);
    float4 pa1 = *reinterpret_cast<const float4*>(Ap + (size_t)64 * lda);
    float4 pb0 = *reinterpret_cast<const float4*>(Bp);
    float4 pb1 = *reinterpret_cast<const float4*>(Bp + (size_t)64 * ldb);
    cvt_store(As32, lrow,      kc, pa0);
    cvt_store(As32, lrow + 64, kc, pa1);
    cvt_store(Bs32, lrow,      kc, pb0);
    cvt_store(Bs32, lrow + 64, kc, pb1);
    __syncthreads();

    int stage = 0;
    for (int k0 = 0; k0 < K; k0 += 16) {
        const bool hasNext = (k0 + 16 < K);
        if (hasNext) {  // issue global loads early; complete under MMAs
            pa0 = *reinterpret_cast<const float4*>(Ap + k0 + 16);
            pa1 = *reinterpret_cast<const float4*>(Ap + (size_t)64 * lda + k0 + 16);
            pb0 = *reinterpret_cast<const float4*>(Bp + k0 + 16);
            pb1 = *reinterpret_cast<const float4*>(Bp + (size_t)64 * ldb + k0 + 16);
        }

        const unsigned soff = stage * (STAGE_U32 * 4);
        // 3 split passes: (Ah,Bh), (Al,Bh), (Ah,Bl); lo slab at +32 bytes
#pragma unroll
        for (int s = 0; s < 3; s++) {
            const unsigned ao = (s == 1) ? 32u : 0u;
            const unsigned bo = (s == 2) ? 32u : 0u;
            unsigned af[4][4], bfr[4][2];
#pragma unroll
            for (int mt = 0; mt < 4; mt++)
                ldsm_x4(af[mt][0], af[mt][1], af[mt][2], af[mt][3],
                        aAddr[mt] + soff + ao);
            ldsm_x4(bfr[0][0], bfr[0][1], bfr[1][0], bfr[1][1], bAddr[0] + soff + bo);
            ldsm_x4(bfr[2][0], bfr[2][1], bfr[3][0], bfr[3][1], bAddr[1] + soff + bo);
#pragma unroll
            for (int mt = 0; mt < 4; mt++)
#pragma unroll
                for (int nt = 0; nt < 4; nt++)
                    mma16816(acc[mt][nt], af[mt], bfr[nt]);
        }

        if (hasNext) {
            unsigned* An = As32 + (stage ^ 1) * STAGE_U32;
            unsigned* Bn = Bs32 + (stage ^ 1) * STAGE_U32;
            cvt_store(An, lrow,      kc, pa0);
            cvt_store(An, lrow + 64, kc, pa1);
            cvt_store(Bn, lrow,      kc, pb0);
            cvt_store(Bn, lrow + 64, kc, pb1);
            stage ^= 1;
            __syncthreads();
        }
    }

    // epilogue (float2-vectorized: col pairs are contiguous)
#pragma unroll
    for (int mt = 0; mt < 4; mt++) {
#pragma unroll
        for (int nt = 0; nt < 4; nt++) {
            const float* d = acc[mt][nt];
            const int gc = bx * 128 + warpN + nt * 8 + tg * 2;
#pragma unroll
            for (int half = 0; half < 2; half++) {
                const int gr = by * 128 + warpM + mt * 16 + g + half * 8;
                float* cp = C + (size_t)gr * ldc + gc;
                float2 v; v.x = d[half * 2]; v.y = d[half * 2 + 1];
                if (EPI == 0) {
                    v.x += bias0[gc]; v.y += bias0[gc + 1];
                    float2 rs = *reinterpret_cast<const float2*>(
                        resid + (size_t)gr * ldc + gc);
                    v.x = 0.5f * v.x * (1.f + erff(v.x * 0.70710678118654752f)) + rs.x;
                    v.y = 0.5f * v.y * (1.f + erff(v.y * 0.70710678118654752f)) + rs.y;
                } else if (EPI == 1) {
                    v.x += bias0[gc]; v.y += bias0[gc + 1];
                } else if (EPI == 2) {
                    v.x += bias0[gc] + bias1[gc]; v.y += bias0[gc + 1] + bias1[gc + 1];
                } else {
                    float2 old = *reinterpret_cast<const float2*>(cp);
                    v.x += old.x; v.y += old.y;
                }
                *reinterpret_cast<float2*>(cp) = v;
            }
        }
    }
}

// ---------------------------------------------------------------------------
// LSTM pointwise cell update, float4-vectorized (4 hidden units / thread).
// ---------------------------------------------------------------------------
__global__ __launch_bounds__(256) void lstm_cell_kernel(
    const float* __restrict__ gb, float* __restrict__ h, float* __restrict__ c,
    float* __restrict__ X, int t, int first)
{
    const int idx4 = blockIdx.x * blockDim.x + threadIdx.x;  // NBM*64
    const int bm = idx4 >> 6;
    const int j4 = (idx4 & 63) * 4;
    const float* g = gb + (size_t)(bm * 6 + t) * 1024;
    const float4 gi = *reinterpret_cast<const float4*>(g + j4);
    const float4 gf = *reinterpret_cast<const float4*>(g + 256 + j4);
    const float4 gg = *reinterpret_cast<const float4*>(g + 512 + j4);
    const float4 go = *reinterpret_cast<const float4*>(g + 768 + j4);
    float4 cold;
    if (first) { cold.x = cold.y = cold.z = cold.w = 0.f; }
    else cold = *reinterpret_cast<const float4*>(c + bm * 256 + j4);
    float4 cn, hn;
#define CELL(e) { \
    float si = 1.f / (1.f + expf(-gi.e)); \
    float sf = 1.f / (1.f + expf(-gf.e)); \
    float so = 1.f / (1.f + expf(-go.e)); \
    cn.e = sf * cold.e + si * tanhf(gg.e); \
    hn.e = so * tanhf(cn.e); }
    CELL(x) CELL(y) CELL(z) CELL(w)
#undef CELL
    *reinterpret_cast<float4*>(c + bm * 256 + j4) = cn;
    *reinterpret_cast<float4*>(h + bm * 256 + j4) = hn;
    *reinterpret_cast<float4*>(X + (size_t)(bm * 6 + t) * 256 + j4) = hn;
}

__global__ __launch_bounds__(256) void final1_kernel(
    const float* __restrict__ X, const float* __restrict__ Wv,
    const float* __restrict__ bv, const float* __restrict__ Ws,
    const float* __restrict__ bs, float* __restrict__ score)
{
    const int warp = threadIdx.x >> 5;
    const int lane = threadIdx.x & 31;
    const int bm = blockIdx.x * 8 + warp;
    float wv[8];
#pragma unroll
    for (int u = 0; u < 8; u++) wv[u] = Wv[lane + u * 32];
    float acc = 0.f;
#pragma unroll
    for (int t = 0; t < 6; t++) {
        const float* row = X + (size_t)(bm * 6 + t) * 256;
        float p = 0.f;
#pragma unroll
        for (int u = 0; u < 8; u++) p = fmaf(row[lane + u * 32], wv[u], p);
#pragma unroll
        for (int o = 16; o; o >>= 1) p += __shfl_xor_sync(0xFFFFFFFFu, p, o);
        acc = fmaf(Ws[t], p + bv[0], acc);
    }
    if (lane == 0) score[bm] = acc + bs[0];
}

__global__ __launch_bounds__(256) void final2_kernel(
    const float* __restrict__ score, float* __restrict__ out)
{
    __shared__ float s[256];
    s[threadIdx.x] = score[blockIdx.x * 256 + threadIdx.x];
    __syncthreads();
    for (int o = 128; o; o >>= 1) {
        if (threadIdx.x < o) s[threadIdx.x] += s[threadIdx.x + o];
        __syncthreads();
    }
    if (threadIdx.x == 0) out[blockIdx.x] = s[0] * (1.f / 256.f);
}

extern "C" void kernel_launch(void* const* d_in, const int* in_sizes, int n_in,
                              void* d_out, int out_size)
{
    (void)in_sizes; (void)n_in; (void)out_size;
    const float* swin = (const float*)d_in[0];
    const float* conv = (const float*)d_in[1];
    const float* Wc   = (const float*)d_in[2];
    const float* bc   = (const float*)d_in[3];
    const float* Win  = (const float*)d_in[4];
    const float* b_in = (const float*)d_in[5];
    const float* Wih  = (const float*)d_in[6];
    const float* Whh  = (const float*)d_in[7];
    const float* bih  = (const float*)d_in[8];
    const float* bhh  = (const float*)d_in[9];
    const float* Wv   = (const float*)d_in[10];
    const float* bv   = (const float*)d_in[11];
    const float* Ws   = (const float*)d_in[12];
    const float* bs   = (const float*)d_in[13];
    float* out = (float*)d_out;

    float *bufA, *bufX, *h, *c, *score;
    cudaGetSymbolAddress((void**)&bufA, g_bufA);
    cudaGetSymbolAddress((void**)&bufX, g_bufX);
    cudaGetSymbolAddress((void**)&h, g_h);
    cudaGetSymbolAddress((void**)&c, g_c);
    cudaGetSymbolAddress((void**)&score, g_score);

    // 1) bufA = swin + gelu(conv @ Wc^T + bc)   [49152,1024]
    bgemm_kernel<0><<<dim3(EMBED / 128, NROWS / 128), 256>>>(
        conv, EMBED, Wc, EMBED, bufA, EMBED, EMBED, bc, nullptr, swin);

    // 2) bufX = bufA @ Win^T + b_in             [49152,256]
    bgemm_kernel<1><<<dim3(INDIM / 128, NROWS / 128), 256>>>(
        bufA, EMBED, Win, EMBED, bufX, INDIM, EMBED, b_in, nullptr, nullptr);

    // 3) LSTM layers
    for (int l = 0; l < 3; l++) {
        const float* WihL = Wih + (size_t)l * 4 * HID * INDIM;
        const float* WhhL = Whh + (size_t)l * 4 * HID * HID;
        bgemm_kernel<2><<<dim3(4 * HID / 128, NROWS / 128), 256>>>(
            bufX, INDIM, WihL, INDIM, bufA, 4 * HID, INDIM,
            bih + l * 4 * HID, bhh + l * 4 * HID, nullptr);
        for (int t = 0; t < 6; t++) {
            if (t > 0) {
                bgemm_kernel<3><<<dim3(4 * HID / 128, NBM / 128), 256>>>(
                    h, HID, WhhL, HID, bufA + t * 4 * HID, NVIEW * 4 * HID, HID,
                    nullptr, nullptr, nullptr);
            }
            lstm_cell_kernel<<<NBM * 64 / 256, 256>>>(bufA, h, c, bufX, t, t == 0 ? 1 : 0);
        }
    }

    // 4) heads + reduction
    final1_kernel<<<NBM / 8, 256>>>(bufX, Wv, bv, Ws, bs, score);
    final2_kernel<<<32, 256>>>(score, out);
}